// round 1
// baseline (speedup 1.0000x reference)
#include <cuda_runtime.h>
#include <math.h>

#define NQ   1024
#define NR   50000
#define CCH  7
#define LL   96
#define KDIM 672      // 7*96
#define TOPK 20

// ---------------- scratch (no allocations allowed) ----------------
__device__ float g_qn[(size_t)NQ * KDIM];
__device__ float g_rn[(size_t)NR * KDIM];
__device__ float g_sims[(size_t)NQ * NR];
__device__ int   g_idx[NQ * TOPK];

// ---------------- encode: z-norm per (row, channel) over L, then row L2-norm ----------------
// one block of 96 threads per sample; thread t owns time index t across all 7 channels.
__global__ void encode_kernel(const float* __restrict__ X, float* __restrict__ out)
{
    int n = blockIdx.x;
    int t = threadIdx.x;           // 0..95
    int warp = t >> 5, lane = t & 31;
    const float* row = X + (size_t)n * KDIM;

    float v[CCH];
#pragma unroll
    for (int c = 0; c < CCH; c++) v[c] = row[c * LL + t];

    __shared__ float sSum[CCH][3];
    __shared__ float sSq[CCH][3];

#pragma unroll
    for (int c = 0; c < CCH; c++) {
        float s = v[c], q = v[c] * v[c];
#pragma unroll
        for (int o = 16; o > 0; o >>= 1) {
            s += __shfl_down_sync(0xffffffffu, s, o);
            q += __shfl_down_sync(0xffffffffu, q, o);
        }
        if (lane == 0) { sSum[c][warp] = s; sSq[c][warp] = q; }
    }
    __syncthreads();

    float an[CCH];
    float part = 0.f;
#pragma unroll
    for (int c = 0; c < CCH; c++) {
        float s = sSum[c][0] + sSum[c][1] + sSum[c][2];
        float q = sSq[c][0] + sSq[c][1] + sSq[c][2];
        float mean = s * (1.0f / LL);
        float var  = (q - s * mean) * (1.0f / (LL - 1));   // ddof=1
        var = fmaxf(var, 0.0f);
        float std  = sqrtf(var) + 1e-6f;
        an[c] = (v[c] - mean) / std;
        part += an[c] * an[c];
    }

    // row L2 norm over all 672
#pragma unroll
    for (int o = 16; o > 0; o >>= 1) part += __shfl_down_sync(0xffffffffu, part, o);
    __shared__ float sN[3];
    if (lane == 0) sN[warp] = part;
    __syncthreads();
    float norm = sqrtf(sN[0] + sN[1] + sN[2]);
    float inv = 1.0f / fmaxf(norm, 1e-12f);

    float* orow = out + (size_t)n * KDIM;
#pragma unroll
    for (int c = 0; c < CCH; c++) orow[c * LL + t] = an[c] * inv;
}

// ---------------- SGEMM: C[M,N] = A[M,K] * B[N,K]^T, fp32, 128x128x8 tile, 8x8/thread ----------------
__global__ void __launch_bounds__(256) sgemm_nt(const float* __restrict__ A,
                                                const float* __restrict__ B,
                                                float* __restrict__ C)
{
    __shared__ __align__(16) float As[8][132];  // +4 pad: conflict-free STS, keeps 16B align (528B row)
    __shared__ __align__(16) float Bs[8][132];

    int tid = threadIdx.x;
    int tx = tid & 15;          // 0..15  -> N
    int ty = tid >> 4;          // 0..15  -> M
    int bm = blockIdx.y * 128;
    int bn = blockIdx.x * 128;

    int lRow = tid >> 1;        // 0..127
    int lCol = (tid & 1) << 2;  // 0 or 4

    const float* Ap = A + (size_t)(bm + lRow) * KDIM + lCol;
    int brow = bn + lRow;
    bool bvalid = brow < NR;
    const float* Bp = B + (size_t)(bvalid ? brow : 0) * KDIM + lCol;

    float acc[8][8];
#pragma unroll
    for (int i = 0; i < 8; i++)
#pragma unroll
        for (int j = 0; j < 8; j++) acc[i][j] = 0.f;

    for (int k0 = 0; k0 < KDIM; k0 += 8) {
        float4 a4 = *(const float4*)(Ap + k0);
        float4 b4 = make_float4(0.f, 0.f, 0.f, 0.f);
        if (bvalid) b4 = *(const float4*)(Bp + k0);

        As[lCol + 0][lRow] = a4.x; As[lCol + 1][lRow] = a4.y;
        As[lCol + 2][lRow] = a4.z; As[lCol + 3][lRow] = a4.w;
        Bs[lCol + 0][lRow] = b4.x; Bs[lCol + 1][lRow] = b4.y;
        Bs[lCol + 2][lRow] = b4.z; Bs[lCol + 3][lRow] = b4.w;
        __syncthreads();

#pragma unroll
        for (int kk = 0; kk < 8; kk++) {
            float a[8], bb[8];
            *(float4*)&a[0]  = *(const float4*)&As[kk][(ty << 2)];
            *(float4*)&a[4]  = *(const float4*)&As[kk][64 + (ty << 2)];
            *(float4*)&bb[0] = *(const float4*)&Bs[kk][(tx << 2)];
            *(float4*)&bb[4] = *(const float4*)&Bs[kk][64 + (tx << 2)];
#pragma unroll
            for (int i = 0; i < 8; i++)
#pragma unroll
                for (int j = 0; j < 8; j++)
                    acc[i][j] = fmaf(a[i], bb[j], acc[i][j]);
        }
        __syncthreads();
    }

#pragma unroll
    for (int ih = 0; ih < 2; ih++)
#pragma unroll
        for (int ii = 0; ii < 4; ii++) {
            int i = ih * 4 + ii;
            int gr = bm + ih * 64 + (ty << 2) + ii;     // M=1024, always in-bounds
            float* Crow = C + (size_t)gr * NR;
#pragma unroll
            for (int jh = 0; jh < 2; jh++) {
                int gc = bn + jh * 64 + (tx << 2);
                if (gc + 3 < NR) {
                    float4 v = make_float4(acc[i][jh * 4 + 0], acc[i][jh * 4 + 1],
                                           acc[i][jh * 4 + 2], acc[i][jh * 4 + 3]);
                    *(float4*)(Crow + gc) = v;
                } else {
#pragma unroll
                    for (int j = 0; j < 4; j++)
                        if (gc + j < NR) Crow[gc + j] = acc[i][jh * 4 + j];
                }
            }
        }
}

// ---------------- top-k (k=20) + softmax per row ----------------
// one block of 256 threads per query row. Per-thread sorted top-20 (local mem),
// then 20 rounds of block argmax over per-thread heads. Tie-break: lower index.
__global__ void __launch_bounds__(256) topk_kernel(const float* __restrict__ sims,
                                                   float* __restrict__ wout,
                                                   int* __restrict__ idxout)
{
    int b = blockIdx.x;
    int tid = threadIdx.x;
    const float* row = sims + (size_t)b * NR;

    float lv[TOPK];
    int   li[TOPK];
#pragma unroll
    for (int j = 0; j < TOPK; j++) { lv[j] = -3.402823466e38f; li[j] = 0x7fffffff; }

    for (int n = tid; n < NR; n += 256) {
        float v = row[n];
        if (v > lv[TOPK - 1]) {
            int p = TOPK - 1;
            while (p > 0 && lv[p - 1] < v) {
                lv[p] = lv[p - 1]; li[p] = li[p - 1]; p--;
            }
            lv[p] = v; li[p] = n;
        }
    }

    __shared__ float cV[256 * TOPK];
    __shared__ int   cI[256 * TOPK];
    __shared__ float sV[256];
    __shared__ int   sI[256];
    __shared__ int   sT[256];
    __shared__ float oV[TOPK];
    __shared__ int   oI[TOPK];
    __shared__ int   winner;

#pragma unroll
    for (int j = 0; j < TOPK; j++) { cV[tid * TOPK + j] = lv[j]; cI[tid * TOPK + j] = li[j]; }

    int head = 0;
    for (int r = 0; r < TOPK; r++) {
        __syncthreads();
        float mv = (head < TOPK) ? cV[tid * TOPK + head] : -3.402823466e38f;
        int   mi = (head < TOPK) ? cI[tid * TOPK + head] : 0x7fffffff;
        sV[tid] = mv; sI[tid] = mi; sT[tid] = tid;
        __syncthreads();
        for (int s = 128; s > 0; s >>= 1) {
            if (tid < s) {
                float v2 = sV[tid + s]; int i2 = sI[tid + s];
                if (v2 > sV[tid] || (v2 == sV[tid] && i2 < sI[tid])) {
                    sV[tid] = v2; sI[tid] = i2; sT[tid] = sT[tid + s];
                }
            }
            __syncthreads();
        }
        if (tid == 0) { oV[r] = sV[0]; oI[r] = sI[0]; winner = sT[0]; }
        __syncthreads();
        if (tid == winner) head++;
    }
    __syncthreads();

    if (tid == 0) {
        float m = oV[0];                     // sorted descending -> max first
        float e[TOPK], s = 0.f;
#pragma unroll
        for (int j = 0; j < TOPK; j++) { e[j] = expf(oV[j] - m); s += e[j]; }
        float inv = 1.0f / s;
#pragma unroll
        for (int j = 0; j < TOPK; j++) {
            wout[b * TOPK + j]   = e[j] * inv;
            idxout[b * TOPK + j] = oI[j];
        }
    }
}

// ---------------- gather: Yk[b,j] = Y_train[idx[b,j]] (672 contiguous floats) ----------------
__global__ void gather_kernel(const float* __restrict__ Y,
                              const int* __restrict__ idx,
                              float* __restrict__ out)
{
    int pair = blockIdx.x;                  // 0 .. NQ*TOPK-1
    int src = idx[pair];
    const float4* s = (const float4*)(Y + (size_t)src * KDIM);
    float4* d = (float4*)(out + (size_t)pair * KDIM);
    if (threadIdx.x < KDIM / 4) d[threadIdx.x] = s[threadIdx.x];
}

// ---------------- launch ----------------
extern "C" void kernel_launch(void* const* d_in, const int* in_sizes, int n_in,
                              void* d_out, int out_size)
{
    const float* x  = (const float*)d_in[0];   // [1024,7,96]
    const float* Xt = (const float*)d_in[1];   // [50000,7,96]
    const float* Yt = (const float*)d_in[2];   // [50000,96,7]
    float* out = (float*)d_out;                // [20480 weights | 13762560 Yk]

    float *qn, *rn, *sims; int* idx;
    cudaGetSymbolAddress((void**)&qn,   g_qn);
    cudaGetSymbolAddress((void**)&rn,   g_rn);
    cudaGetSymbolAddress((void**)&sims, g_sims);
    cudaGetSymbolAddress((void**)&idx,  g_idx);

    encode_kernel<<<NR, 96>>>(Xt, rn);
    encode_kernel<<<NQ, 96>>>(x, qn);

    dim3 grid((NR + 127) / 128, NQ / 128);
    sgemm_nt<<<grid, 256>>>(qn, rn, sims);

    topk_kernel<<<NQ, 256>>>(sims, out, idx);

    gather_kernel<<<NQ * TOPK, 192>>>(Yt, idx, out + NQ * TOPK);
}

// round 2
// speedup vs baseline: 1.0287x; 1.0287x over previous
#include <cuda_runtime.h>
#include <math.h>

#define NQ   1024
#define NR   50000
#define CCH  7
#define LL   96
#define KDIM 672      // 7*96
#define TOPK 20
#define NT   (KDIM / 8)   // 84 k-tiles

// ---------------- scratch (no allocations allowed) ----------------
__device__ float g_qn[(size_t)NQ * KDIM];
__device__ float g_rn[(size_t)NR * KDIM];
__device__ float g_sims[(size_t)NQ * NR];
__device__ int   g_idx[NQ * TOPK];

// ---------------- encode: z-norm per (row, channel) over L, then row L2-norm ----------------
__global__ void encode_kernel(const float* __restrict__ X, float* __restrict__ out)
{
    int n = blockIdx.x;
    int t = threadIdx.x;           // 0..95
    int warp = t >> 5, lane = t & 31;
    const float* row = X + (size_t)n * KDIM;

    float v[CCH];
#pragma unroll
    for (int c = 0; c < CCH; c++) v[c] = row[c * LL + t];

    __shared__ float sSum[CCH][3];
    __shared__ float sSq[CCH][3];

#pragma unroll
    for (int c = 0; c < CCH; c++) {
        float s = v[c], q = v[c] * v[c];
#pragma unroll
        for (int o = 16; o > 0; o >>= 1) {
            s += __shfl_down_sync(0xffffffffu, s, o);
            q += __shfl_down_sync(0xffffffffu, q, o);
        }
        if (lane == 0) { sSum[c][warp] = s; sSq[c][warp] = q; }
    }
    __syncthreads();

    float an[CCH];
    float part = 0.f;
#pragma unroll
    for (int c = 0; c < CCH; c++) {
        float s = sSum[c][0] + sSum[c][1] + sSum[c][2];
        float q = sSq[c][0] + sSq[c][1] + sSq[c][2];
        float mean = s * (1.0f / LL);
        float var  = (q - s * mean) * (1.0f / (LL - 1));   // ddof=1
        var = fmaxf(var, 0.0f);
        float std  = sqrtf(var) + 1e-6f;
        an[c] = (v[c] - mean) / std;
        part += an[c] * an[c];
    }

#pragma unroll
    for (int o = 16; o > 0; o >>= 1) part += __shfl_down_sync(0xffffffffu, part, o);
    __shared__ float sN[3];
    if (lane == 0) sN[warp] = part;
    __syncthreads();
    float norm = sqrtf(sN[0] + sN[1] + sN[2]);
    float inv = 1.0f / fmaxf(norm, 1e-12f);

    float* orow = out + (size_t)n * KDIM;
#pragma unroll
    for (int c = 0; c < CCH; c++) orow[c * LL + t] = an[c] * inv;
}

// ---------------- pipelined SGEMM: C[M,N] = A[M,K] * B[N,K]^T ----------------
// 128x128x8 tile, 8x8/thread, smem double-buffered (1 sync/tile),
// register fragment double-buffered, gmem prefetch issued before compute.
__global__ void __launch_bounds__(256) sgemm_nt(const float* __restrict__ A,
                                                const float* __restrict__ B,
                                                float* __restrict__ C)
{
    __shared__ __align__(16) float As[2][8][132];  // +4 pad: conflict-free STS
    __shared__ __align__(16) float Bs[2][8][132];

    int tid = threadIdx.x;
    int tx = tid & 15;          // 0..15  -> N
    int ty = tid >> 4;          // 0..15  -> M
    int bm = blockIdx.y * 128;
    int bn = blockIdx.x * 128;

    int lRow = tid >> 1;        // 0..127
    int lCol = (tid & 1) << 2;  // 0 or 4

    const float* Ap = A + (size_t)(bm + lRow) * KDIM + lCol;
    int brow = bn + lRow;
    bool bvalid = brow < NR;
    const float* Bp = B + (size_t)(bvalid ? brow : 0) * KDIM + lCol;

    // ---- prologue: load tile 0 into buf 0 ----
    float4 a4 = *(const float4*)Ap;
    float4 b4 = bvalid ? *(const float4*)Bp : make_float4(0.f, 0.f, 0.f, 0.f);

    As[0][lCol + 0][lRow] = a4.x; As[0][lCol + 1][lRow] = a4.y;
    As[0][lCol + 2][lRow] = a4.z; As[0][lCol + 3][lRow] = a4.w;
    Bs[0][lCol + 0][lRow] = b4.x; Bs[0][lCol + 1][lRow] = b4.y;
    Bs[0][lCol + 2][lRow] = b4.z; Bs[0][lCol + 3][lRow] = b4.w;
    __syncthreads();

    float acc[8][8];
#pragma unroll
    for (int i = 0; i < 8; i++)
#pragma unroll
        for (int j = 0; j < 8; j++) acc[i][j] = 0.f;

    float fa[2][8], fb[2][8];
    int buf = 0;

#define FRAG_LOAD(slot, kk) do {                                              \
        *(float4*)(&fa[slot][0]) = *(const float4*)(&As[buf][kk][(ty << 2)]);      \
        *(float4*)(&fa[slot][4]) = *(const float4*)(&As[buf][kk][64 + (ty << 2)]); \
        *(float4*)(&fb[slot][0]) = *(const float4*)(&Bs[buf][kk][(tx << 2)]);      \
        *(float4*)(&fb[slot][4]) = *(const float4*)(&Bs[buf][kk][64 + (tx << 2)]); \
    } while (0)

    FRAG_LOAD(0, 0);

    for (int t = 0; t < NT; t++) {
        // prefetch next tile (issued before compute so LDG latency hides)
        if (t + 1 < NT) {
            a4 = *(const float4*)(Ap + (t + 1) * 8);
            b4 = bvalid ? *(const float4*)(Bp + (t + 1) * 8)
                        : make_float4(0.f, 0.f, 0.f, 0.f);
        }

#pragma unroll
        for (int kk = 0; kk < 8; kk++) {
            int cur = kk & 1, nxt = cur ^ 1;
            if (kk < 7) FRAG_LOAD(nxt, kk + 1);
#pragma unroll
            for (int i = 0; i < 8; i++)
#pragma unroll
                for (int j = 0; j < 8; j++)
                    acc[i][j] = fmaf(fa[cur][i], fb[cur][j], acc[i][j]);
        }

        if (t + 1 < NT) {
            int nb = buf ^ 1;
            As[nb][lCol + 0][lRow] = a4.x; As[nb][lCol + 1][lRow] = a4.y;
            As[nb][lCol + 2][lRow] = a4.z; As[nb][lCol + 3][lRow] = a4.w;
            Bs[nb][lCol + 0][lRow] = b4.x; Bs[nb][lCol + 1][lRow] = b4.y;
            Bs[nb][lCol + 2][lRow] = b4.z; Bs[nb][lCol + 3][lRow] = b4.w;
            __syncthreads();
            buf = nb;
            FRAG_LOAD(0, 0);
        }
    }
#undef FRAG_LOAD

    // ---- epilogue ----
#pragma unroll
    for (int ih = 0; ih < 2; ih++)
#pragma unroll
        for (int ii = 0; ii < 4; ii++) {
            int i = ih * 4 + ii;
            int gr = bm + ih * 64 + (ty << 2) + ii;     // M=1024, always in-bounds
            float* Crow = C + (size_t)gr * NR;
#pragma unroll
            for (int jh = 0; jh < 2; jh++) {
                int gc = bn + jh * 64 + (tx << 2);
                if (gc + 3 < NR) {
                    float4 v = make_float4(acc[i][jh * 4 + 0], acc[i][jh * 4 + 1],
                                           acc[i][jh * 4 + 2], acc[i][jh * 4 + 3]);
                    *(float4*)(Crow + gc) = v;
                } else {
#pragma unroll
                    for (int j = 0; j < 4; j++)
                        if (gc + j < NR) Crow[gc + j] = acc[i][jh * 4 + j];
                }
            }
        }
}

// ---------------- top-k (k=20) + softmax per row ----------------
__global__ void __launch_bounds__(256) topk_kernel(const float* __restrict__ sims,
                                                   float* __restrict__ wout,
                                                   int* __restrict__ idxout)
{
    int b = blockIdx.x;
    int tid = threadIdx.x;
    const float* row = sims + (size_t)b * NR;

    float lv[TOPK];
    int   li[TOPK];
#pragma unroll
    for (int j = 0; j < TOPK; j++) { lv[j] = -3.402823466e38f; li[j] = 0x7fffffff; }

    for (int n = tid; n < NR; n += 256) {
        float v = row[n];
        if (v > lv[TOPK - 1]) {
            int p = TOPK - 1;
            while (p > 0 && lv[p - 1] < v) {
                lv[p] = lv[p - 1]; li[p] = li[p - 1]; p--;
            }
            lv[p] = v; li[p] = n;
        }
    }

    __shared__ float cV[256 * TOPK];
    __shared__ int   cI[256 * TOPK];
    __shared__ float sV[256];
    __shared__ int   sI[256];
    __shared__ int   sT[256];
    __shared__ float oV[TOPK];
    __shared__ int   oI[TOPK];
    __shared__ int   winner;

#pragma unroll
    for (int j = 0; j < TOPK; j++) { cV[tid * TOPK + j] = lv[j]; cI[tid * TOPK + j] = li[j]; }

    int head = 0;
    for (int r = 0; r < TOPK; r++) {
        __syncthreads();
        float mv = (head < TOPK) ? cV[tid * TOPK + head] : -3.402823466e38f;
        int   mi = (head < TOPK) ? cI[tid * TOPK + head] : 0x7fffffff;
        sV[tid] = mv; sI[tid] = mi; sT[tid] = tid;
        __syncthreads();
        for (int s = 128; s > 0; s >>= 1) {
            if (tid < s) {
                float v2 = sV[tid + s]; int i2 = sI[tid + s];
                if (v2 > sV[tid] || (v2 == sV[tid] && i2 < sI[tid])) {
                    sV[tid] = v2; sI[tid] = i2; sT[tid] = sT[tid + s];
                }
            }
            __syncthreads();
        }
        if (tid == 0) { oV[r] = sV[0]; oI[r] = sI[0]; winner = sT[0]; }
        __syncthreads();
        if (tid == winner) head++;
    }
    __syncthreads();

    if (tid == 0) {
        float m = oV[0];
        float e[TOPK], s = 0.f;
#pragma unroll
        for (int j = 0; j < TOPK; j++) { e[j] = expf(oV[j] - m); s += e[j]; }
        float inv = 1.0f / s;
#pragma unroll
        for (int j = 0; j < TOPK; j++) {
            wout[b * TOPK + j]   = e[j] * inv;
            idxout[b * TOPK + j] = oI[j];
        }
    }
}

// ---------------- gather: Yk[b,j] = Y_train[idx[b,j]] (672 contiguous floats) ----------------
__global__ void gather_kernel(const float* __restrict__ Y,
                              const int* __restrict__ idx,
                              float* __restrict__ out)
{
    int pair = blockIdx.x;                  // 0 .. NQ*TOPK-1
    int src = idx[pair];
    const float4* s = (const float4*)(Y + (size_t)src * KDIM);
    float4* d = (float4*)(out + (size_t)pair * KDIM);
    if (threadIdx.x < KDIM / 4) d[threadIdx.x] = s[threadIdx.x];
}

// ---------------- launch ----------------
extern "C" void kernel_launch(void* const* d_in, const int* in_sizes, int n_in,
                              void* d_out, int out_size)
{
    const float* x  = (const float*)d_in[0];   // [1024,7,96]
    const float* Xt = (const float*)d_in[1];   // [50000,7,96]
    const float* Yt = (const float*)d_in[2];   // [50000,96,7]
    float* out = (float*)d_out;                // [20480 weights | 13762560 Yk]

    float *qn, *rn, *sims; int* idx;
    cudaGetSymbolAddress((void**)&qn,   g_qn);
    cudaGetSymbolAddress((void**)&rn,   g_rn);
    cudaGetSymbolAddress((void**)&sims, g_sims);
    cudaGetSymbolAddress((void**)&idx,  g_idx);

    encode_kernel<<<NR, 96>>>(Xt, rn);
    encode_kernel<<<NQ, 96>>>(x, qn);

    dim3 grid((NR + 127) / 128, NQ / 128);
    sgemm_nt<<<grid, 256>>>(qn, rn, sims);

    topk_kernel<<<NQ, 256>>>(sims, out, idx);

    gather_kernel<<<NQ * TOPK, 192>>>(Yt, idx, out + NQ * TOPK);
}